// round 10
// baseline (speedup 1.0000x reference)
#include <cuda_runtime.h>
#include <math.h>

#define BB 128
#define TT 256
#define HH 512
#define H3 1536
typedef unsigned long long ull;

__device__ __forceinline__ ull dup2(float x) {
    ull r; asm("mov.b64 %0, {%1, %1};" : "=l"(r) : "f"(x)); return r;
}
__device__ __forceinline__ void ffma2(ull& d, ull a, ull b) {
    asm("fma.rn.f32x2 %0, %1, %2, %0;" : "+l"(d) : "l"(a), "l"(b));
}
__device__ __forceinline__ float2 unpk(ull v) {
    float2 f; asm("mov.b64 {%0, %1}, %2;" : "=f"(f.x), "=f"(f.y) : "l"(v)); return f;
}

__device__ float g_xp[(size_t)BB * TT * H3];
__device__ float g_y [(size_t)BB * TT * HH];
__device__ float g_h [2][BB * HH];
__device__ unsigned g_bar2[4][8];
__device__ unsigned g_dummy;

__global__ void init_k() {
    int i = blockIdx.x * blockDim.x + threadIdx.x;
    if (i < BB * HH) g_h[0][i] = 0.0f;
    if (i < 32) ((unsigned*)g_bar2)[i] = 0u;
}

__global__ void dummy_k() { if (threadIdx.x == 0) g_dummy = 0u; }

// ---- proj: double-buffered FFMA2 GEMM, tile 128x64, BK=16 -------------------
__global__ void __launch_bounds__(256, 3) proj_k(const float* __restrict__ xin,
                                                 const float* __restrict__ Wk,
                                                 const float* __restrict__ bias,
                                                 int useY)
{
    const float* Ain = useY ? (const float*)g_y : xin;
    __shared__ float As[2][16 * 128];
    __shared__ float Bs[2][16 * 64];
    const int tid = threadIdx.x;
    const int m0 = blockIdx.y * 128, n0 = blockIdx.x * 64;
    const int tx = tid & 15, ty = tid >> 4;
    const int my = ty * 8;
    const int mA = tid >> 1, kA = (tid & 1) * 8;
    const int kB = tid >> 4, nB = (tid & 15) * 4;
    const float* aptr = Ain + (size_t)(m0 + mA) * HH + kA;
    const float* bptr = Wk + (size_t)kB * H3 + n0 + nB;

    ull acc[4][4];
#pragma unroll
    for (int p = 0; p < 4; ++p)
#pragma unroll
        for (int j = 0; j < 4; ++j) acc[p][j] = 0ull;

    // preload stage 0
    float4 av0 = *(const float4*)(aptr);
    float4 av1 = *(const float4*)(aptr + 4);
    float4 bv  = *(const float4*)(bptr);
    {
        float* a = As[0]; float* b = Bs[0];
        a[(kA + 0) * 128 + mA] = av0.x; a[(kA + 1) * 128 + mA] = av0.y;
        a[(kA + 2) * 128 + mA] = av0.z; a[(kA + 3) * 128 + mA] = av0.w;
        a[(kA + 4) * 128 + mA] = av1.x; a[(kA + 5) * 128 + mA] = av1.y;
        a[(kA + 6) * 128 + mA] = av1.z; a[(kA + 7) * 128 + mA] = av1.w;
        *(float4*)&b[kB * 64 + nB] = bv;
    }
    __syncthreads();

#pragma unroll 2
    for (int kt = 0; kt < 32; ++kt) {
        const int s = kt & 1;
        if (kt < 31) {   // prefetch next tile (hidden under compute)
            av0 = *(const float4*)(aptr + (kt + 1) * 16);
            av1 = *(const float4*)(aptr + (kt + 1) * 16 + 4);
            bv  = *(const float4*)(bptr + (size_t)((kt + 1) * 16) * H3);
        }
        const float* a = As[s]; const float* b = Bs[s];
#pragma unroll
        for (int k = 0; k < 16; ++k) {
            const ulonglong2* ap = (const ulonglong2*)(a + k * 128 + my);
            ulonglong2 q0 = ap[0], q1 = ap[1];
            ull A0 = q0.x, A1 = q0.y, A2 = q1.x, A3 = q1.y;
            float4 w4 = *(const float4*)(b + k * 64 + tx * 4);
            ull W0 = dup2(w4.x), W1 = dup2(w4.y), W2 = dup2(w4.z), W3 = dup2(w4.w);
            ffma2(acc[0][0], A0, W0); ffma2(acc[0][1], A0, W1);
            ffma2(acc[0][2], A0, W2); ffma2(acc[0][3], A0, W3);
            ffma2(acc[1][0], A1, W0); ffma2(acc[1][1], A1, W1);
            ffma2(acc[1][2], A1, W2); ffma2(acc[1][3], A1, W3);
            ffma2(acc[2][0], A2, W0); ffma2(acc[2][1], A2, W1);
            ffma2(acc[2][2], A2, W2); ffma2(acc[2][3], A2, W3);
            ffma2(acc[3][0], A3, W0); ffma2(acc[3][1], A3, W1);
            ffma2(acc[3][2], A3, W2); ffma2(acc[3][3], A3, W3);
        }
        if (kt < 31) {
            float* an = As[s ^ 1]; float* bn = Bs[s ^ 1];
            an[(kA + 0) * 128 + mA] = av0.x; an[(kA + 1) * 128 + mA] = av0.y;
            an[(kA + 2) * 128 + mA] = av0.z; an[(kA + 3) * 128 + mA] = av0.w;
            an[(kA + 4) * 128 + mA] = av1.x; an[(kA + 5) * 128 + mA] = av1.y;
            an[(kA + 6) * 128 + mA] = av1.z; an[(kA + 7) * 128 + mA] = av1.w;
            *(float4*)&bn[kB * 64 + nB] = bv;
            __syncthreads();
        }
    }

    float4 b4 = *(const float4*)&bias[n0 + tx * 4];
    float bb[4] = {b4.x, b4.y, b4.z, b4.w};
#pragma unroll
    for (int p = 0; p < 4; ++p) {
        float2 u0 = unpk(acc[p][0]), u1 = unpk(acc[p][1]);
        float2 u2 = unpk(acc[p][2]), u3 = unpk(acc[p][3]);
        int rlo = m0 + my + 2 * p;
        float4 o0 = {u0.x + bb[0], u1.x + bb[1], u2.x + bb[2], u3.x + bb[3]};
        float4 o1 = {u0.y + bb[0], u1.y + bb[1], u2.y + bb[2], u3.y + bb[3]};
        *(float4*)&g_xp[(size_t)rlo * H3 + n0 + tx * 4] = o0;
        *(float4*)&g_xp[(size_t)(rlo + 1) * H3 + n0 + tx * 4] = o1;
    }
}

// ---- gru: 8-warp split-K FFMA2, per-warp staging, fast gates -----------------
#define HSTRIDE 516
#define SM_WS   (512 * 48)
#define SM_HS   (32 * HSTRIDE)
#define SM_RP   (8 * 32 * 49)
#define SMEM_FLOATS (SM_WS + SM_HS + SM_RP + 48)

__global__ void __launch_bounds__(256, 1) gru_layer_k(const float* __restrict__ Wu,
                                                      const float* __restrict__ br,
                                                      float* __restrict__ dout,
                                                      int layer, int isLast)
{
    extern __shared__ float sm[];
    float* ws  = sm;
    float* hs  = ws + SM_WS;
    float* rp  = hs + SM_HS;
    float* brs = rp + SM_RP;

    const int tid = threadIdx.x;
    const int g   = blockIdx.x >> 5;
    const int hg  = blockIdx.x & 31;
    const int b0g = g * 32, c0g = hg * 16;
    unsigned* myCnt = &g_bar2[g][hg & 7];

    for (int idx = tid; idx < SM_WS; idx += 256) {
        int k = idx / 48, j = idx % 48;
        ws[idx] = Wu[(size_t)k * H3 + (j >> 4) * HH + c0g + (j & 15)];
    }
    for (int j = tid; j < 48; j += 256)
        brs[j] = br[(j >> 4) * HH + c0g + (j & 15)];
    __syncthreads();

    const int wrp = tid >> 5, lane = tid & 31;
    const int rbase = lane & 7;
    const int c0 = (lane >> 3) * 12;
    const int kbase = wrp * 64;
    const unsigned layerBase = (unsigned)layer * TT;

    for (int t = 0; t < TT; ++t) {
        // xp prefetch (barrier-independent)
        float pz[2], pr[2], ph[2];
#pragma unroll
        for (int q = 0; q < 2; ++q) {
            int idx = tid + q * 256;
            const float* xb = g_xp + ((size_t)(b0g + (idx >> 4)) * TT + t) * H3
                              + (c0g + (idx & 15));
            pz[q] = __ldcs(xb); pr[q] = __ldcs(xb + HH); ph[q] = __ldcs(xb + 2 * HH);
        }

        // spread-counter barrier, REDUX sum poll
        unsigned target = 32u * (layerBase + (unsigned)t);
        if (tid < 8) {
            const unsigned* cp = &g_bar2[g][tid];
            unsigned v;
            do {
                asm volatile("ld.acquire.gpu.global.u32 %0, [%1];" : "=r"(v) : "l"(cp));
            } while (__reduce_add_sync(0xffu, v) < target);
        }
        __syncthreads();

        // stage OWN 64-k slice: lane = batch row, 16 contiguous float4
        {
            const float* src = g_h[t & 1] + (size_t)(b0g + lane) * HH + kbase;
            float* dst = hs + lane * HSTRIDE + kbase;
#pragma unroll
            for (int u = 0; u < 16; ++u)
                ((float4*)dst)[u] = __ldcg(&((const float4*)src)[u]);
        }
        __syncwarp();

        // split-K GEMM over own slice
        ull acc[4][6];
#pragma unroll
        for (int i = 0; i < 4; ++i)
#pragma unroll
            for (int q = 0; q < 6; ++q) acc[i][q] = 0ull;
#pragma unroll 4
        for (int kk = 0; kk < 64; ++kk) {
            int k = kbase + kk;
            const float* hk = hs + k;
            ull A0 = dup2(hk[(rbase +  0) * HSTRIDE]);
            ull A1 = dup2(hk[(rbase +  8) * HSTRIDE]);
            ull A2 = dup2(hk[(rbase + 16) * HSTRIDE]);
            ull A3 = dup2(hk[(rbase + 24) * HSTRIDE]);
            const ulonglong2* wv = (const ulonglong2*)(ws + k * 48 + c0);
            ulonglong2 p0 = wv[0], p1 = wv[1], p2 = wv[2];
            ull w0 = p0.x, w1 = p0.y, w2 = p1.x, w3 = p1.y, w4 = p2.x, w5 = p2.y;
            ffma2(acc[0][0], A0, w0); ffma2(acc[0][1], A0, w1); ffma2(acc[0][2], A0, w2);
            ffma2(acc[0][3], A0, w3); ffma2(acc[0][4], A0, w4); ffma2(acc[0][5], A0, w5);
            ffma2(acc[1][0], A1, w0); ffma2(acc[1][1], A1, w1); ffma2(acc[1][2], A1, w2);
            ffma2(acc[1][3], A1, w3); ffma2(acc[1][4], A1, w4); ffma2(acc[1][5], A1, w5);
            ffma2(acc[2][0], A2, w0); ffma2(acc[2][1], A2, w1); ffma2(acc[2][2], A2, w2);
            ffma2(acc[2][3], A2, w3); ffma2(acc[2][4], A2, w4); ffma2(acc[2][5], A2, w5);
            ffma2(acc[3][0], A3, w0); ffma2(acc[3][1], A3, w1); ffma2(acc[3][2], A3, w2);
            ffma2(acc[3][3], A3, w3); ffma2(acc[3][4], A3, w4); ffma2(acc[3][5], A3, w5);
        }
        float* rpw = rp + wrp * (32 * 49);
#pragma unroll
        for (int i = 0; i < 4; ++i) {
            int row = rbase + 8 * i;
#pragma unroll
            for (int q = 0; q < 6; ++q) {
                float2 u = unpk(acc[i][q]);
                rpw[row * 49 + c0 + 2 * q]     = u.x;
                rpw[row * 49 + c0 + 2 * q + 1] = u.y;
            }
        }
        __syncthreads();

        // reduce + fast gates; write h, release, then y
        float* hdst = g_h[(t + 1) & 1];
        float* yout = isLast ? dout : (float*)g_y;
        float hn[2]; int gbv[2], gcv[2];
#pragma unroll
        for (int q = 0; q < 2; ++q) {
            int idx = tid + q * 256;
            int b = idx >> 4, c = idx & 15;
            gbv[q] = b0g + b; gcv[q] = c0g + c;
            int base = b * 49;
            float rz = brs[c], rr = brs[16 + c], rh = brs[32 + c];
#pragma unroll
            for (int w = 0; w < 8; ++w) {
                int o = w * 1568 + base;
                rz += rp[o + c];
                rr += rp[o + 16 + c];
                rh += rp[o + 32 + c];
            }
            float ez = __expf(-(pz[q] + rz));
            float z = __fdividef(1.0f, 1.0f + ez);
            float er = __expf(-(pr[q] + rr));
            float r = __fdividef(1.0f, 1.0f + er);
            float xa = ph[q] + r * rh;
            xa = fminf(fmaxf(xa, -15.0f), 15.0f);
            float e2 = __expf(2.0f * xa);
            float hh = __fdividef(e2 - 1.0f, e2 + 1.0f);
            float hold = hs[b * HSTRIDE + gcv[q]];
            hn[q] = z * hold + (1.0f - z) * hh;
            hdst[(size_t)gbv[q] * HH + gcv[q]] = hn[q];
        }

        __syncthreads();
        if (tid == 0)
            asm volatile("red.release.gpu.global.add.u32 [%0], %1;"
                         :: "l"(myCnt), "r"(1u) : "memory");

        // y / dout writes drain behind the release
#pragma unroll
        for (int q = 0; q < 2; ++q)
            yout[((size_t)gbv[q] * TT + t) * HH + gcv[q]] = hn[q];
    }
}

__global__ void copy_h_k(float* dout, int out_size) {
    int i = blockIdx.x * blockDim.x + threadIdx.x;
    size_t off = (size_t)BB * TT * HH;
    if (i < BB * HH && (off + i) < (size_t)out_size)
        dout[off + i] = g_h[0][i];
}

extern "C" void kernel_launch(void* const* d_in, const int* in_sizes, int n_in,
                              void* d_out, int out_size) {
    const float* x        = (const float*)d_in[0];
    const float* kernels  = (const float*)d_in[1];
    const float* rkernels = (const float*)d_in[2];
    const float* biases   = (const float*)d_in[3];
    float* out = (float*)d_out;

    cudaFuncSetAttribute(gru_layer_k, cudaFuncAttributeMaxDynamicSharedMemorySize,
                         SMEM_FLOATS * (int)sizeof(float));
    init_k<<<(BB * HH + 255) / 256, 256>>>();
    dummy_k<<<1, 32>>>();   // keep launch order: gru_layer_k stays at ncu index 5

    dim3 pgrid(H3 / 64, (BB * TT) / 128);
    for (int l = 0; l < 3; ++l) {
        proj_k<<<pgrid, 256>>>(x, kernels + (size_t)l * HH * H3,
                               biases + (size_t)l * 2 * H3, l > 0);
        gru_layer_k<<<128, 256, SMEM_FLOATS * (int)sizeof(float)>>>(
            rkernels + (size_t)l * HH * H3,
            biases + (size_t)l * 2 * H3 + H3,
            out, l, (l == 2) ? 1 : 0);
    }
    copy_h_k<<<(BB * HH + 255) / 256, 256>>>(out, out_size);
}

// round 11
// speedup vs baseline: 1.1933x; 1.1933x over previous
#include <cuda_runtime.h>
#include <math.h>

#define BB 128
#define TT 256
#define HH 512
#define H3 1536
typedef unsigned long long ull;

__device__ __forceinline__ ull dup2(float x) {
    ull r; asm("mov.b64 %0, {%1, %1};" : "=l"(r) : "f"(x)); return r;
}
__device__ __forceinline__ void ffma2(ull& d, ull a, ull b) {
    asm("fma.rn.f32x2 %0, %1, %2, %0;" : "+l"(d) : "l"(a), "l"(b));
}
__device__ __forceinline__ float2 unpk(ull v) {
    float2 f; asm("mov.b64 {%0, %1}, %2;" : "=f"(f.x), "=f"(f.y) : "l"(v)); return f;
}

__device__ float g_xp[(size_t)BB * TT * H3];
__device__ float g_y [(size_t)BB * TT * HH];
__device__ float g_h [2][BB * HH];
__device__ unsigned g_bar2[4][8];
__device__ unsigned g_dummy;

__global__ void init_k() {
    int i = blockIdx.x * blockDim.x + threadIdx.x;
    if (i < BB * HH) g_h[0][i] = 0.0f;
    if (i < 32) ((unsigned*)g_bar2)[i] = 0u;
}

__global__ void dummy_k() { if (threadIdx.x == 0) g_dummy = 0u; }

// ---- proj: double-buffered FFMA2 GEMM, tile 128x64, BK=16 (round-10 form) ---
__global__ void __launch_bounds__(256, 3) proj_k(const float* __restrict__ xin,
                                                 const float* __restrict__ Wk,
                                                 const float* __restrict__ bias,
                                                 int useY)
{
    const float* Ain = useY ? (const float*)g_y : xin;
    __shared__ float As[2][16 * 128];
    __shared__ float Bs[2][16 * 64];
    const int tid = threadIdx.x;
    const int m0 = blockIdx.y * 128, n0 = blockIdx.x * 64;
    const int tx = tid & 15, ty = tid >> 4;
    const int my = ty * 8;
    const int mA = tid >> 1, kA = (tid & 1) * 8;
    const int kB = tid >> 4, nB = (tid & 15) * 4;
    const float* aptr = Ain + (size_t)(m0 + mA) * HH + kA;
    const float* bptr = Wk + (size_t)kB * H3 + n0 + nB;

    ull acc[4][4];
#pragma unroll
    for (int p = 0; p < 4; ++p)
#pragma unroll
        for (int j = 0; j < 4; ++j) acc[p][j] = 0ull;

    float4 av0 = *(const float4*)(aptr);
    float4 av1 = *(const float4*)(aptr + 4);
    float4 bv  = *(const float4*)(bptr);
    {
        float* a = As[0]; float* b = Bs[0];
        a[(kA + 0) * 128 + mA] = av0.x; a[(kA + 1) * 128 + mA] = av0.y;
        a[(kA + 2) * 128 + mA] = av0.z; a[(kA + 3) * 128 + mA] = av0.w;
        a[(kA + 4) * 128 + mA] = av1.x; a[(kA + 5) * 128 + mA] = av1.y;
        a[(kA + 6) * 128 + mA] = av1.z; a[(kA + 7) * 128 + mA] = av1.w;
        *(float4*)&b[kB * 64 + nB] = bv;
    }
    __syncthreads();

#pragma unroll 2
    for (int kt = 0; kt < 32; ++kt) {
        const int s = kt & 1;
        if (kt < 31) {
            av0 = *(const float4*)(aptr + (kt + 1) * 16);
            av1 = *(const float4*)(aptr + (kt + 1) * 16 + 4);
            bv  = *(const float4*)(bptr + (size_t)((kt + 1) * 16) * H3);
        }
        const float* a = As[s]; const float* b = Bs[s];
#pragma unroll
        for (int k = 0; k < 16; ++k) {
            const ulonglong2* ap = (const ulonglong2*)(a + k * 128 + my);
            ulonglong2 q0 = ap[0], q1 = ap[1];
            ull A0 = q0.x, A1 = q0.y, A2 = q1.x, A3 = q1.y;
            float4 w4 = *(const float4*)(b + k * 64 + tx * 4);
            ull W0 = dup2(w4.x), W1 = dup2(w4.y), W2 = dup2(w4.z), W3 = dup2(w4.w);
            ffma2(acc[0][0], A0, W0); ffma2(acc[0][1], A0, W1);
            ffma2(acc[0][2], A0, W2); ffma2(acc[0][3], A0, W3);
            ffma2(acc[1][0], A1, W0); ffma2(acc[1][1], A1, W1);
            ffma2(acc[1][2], A1, W2); ffma2(acc[1][3], A1, W3);
            ffma2(acc[2][0], A2, W0); ffma2(acc[2][1], A2, W1);
            ffma2(acc[2][2], A2, W2); ffma2(acc[2][3], A2, W3);
            ffma2(acc[3][0], A3, W0); ffma2(acc[3][1], A3, W1);
            ffma2(acc[3][2], A3, W2); ffma2(acc[3][3], A3, W3);
        }
        if (kt < 31) {
            float* an = As[s ^ 1]; float* bn = Bs[s ^ 1];
            an[(kA + 0) * 128 + mA] = av0.x; an[(kA + 1) * 128 + mA] = av0.y;
            an[(kA + 2) * 128 + mA] = av0.z; an[(kA + 3) * 128 + mA] = av0.w;
            an[(kA + 4) * 128 + mA] = av1.x; an[(kA + 5) * 128 + mA] = av1.y;
            an[(kA + 6) * 128 + mA] = av1.z; an[(kA + 7) * 128 + mA] = av1.w;
            *(float4*)&bn[kB * 64 + nB] = bv;
            __syncthreads();
        }
    }

    float4 b4 = *(const float4*)&bias[n0 + tx * 4];
    float bb[4] = {b4.x, b4.y, b4.z, b4.w};
#pragma unroll
    for (int p = 0; p < 4; ++p) {
        float2 u0 = unpk(acc[p][0]), u1 = unpk(acc[p][1]);
        float2 u2 = unpk(acc[p][2]), u3 = unpk(acc[p][3]);
        int rlo = m0 + my + 2 * p;
        float4 o0 = {u0.x + bb[0], u1.x + bb[1], u2.x + bb[2], u3.x + bb[3]};
        float4 o1 = {u0.y + bb[0], u1.y + bb[1], u2.y + bb[2], u3.y + bb[3]};
        *(float4*)&g_xp[(size_t)rlo * H3 + n0 + tx * 4] = o0;
        *(float4*)&g_xp[(size_t)(rlo + 1) * H3 + n0 + tx * 4] = o1;
    }
}

// ---- gru: round-9 coalesced staging + fast gates + deferred y ---------------
#define HSTRIDE 516
#define SM_WS   (512 * 48)
#define SM_HS   (32 * HSTRIDE)
#define SM_RP   (8 * 32 * 49)
#define SMEM_FLOATS (SM_WS + SM_HS + SM_RP + 48)

__global__ void __launch_bounds__(256, 1) gru_layer_k(const float* __restrict__ Wu,
                                                      const float* __restrict__ br,
                                                      float* __restrict__ dout,
                                                      int layer, int isLast)
{
    extern __shared__ float sm[];
    float* ws  = sm;
    float* hs  = ws + SM_WS;
    float* rp  = hs + SM_HS;
    float* brs = rp + SM_RP;

    const int tid = threadIdx.x;
    const int g   = blockIdx.x >> 5;
    const int hg  = blockIdx.x & 31;
    const int b0g = g * 32, c0g = hg * 16;
    unsigned* myCnt = &g_bar2[g][hg & 7];

    for (int idx = tid; idx < SM_WS; idx += 256) {
        int k = idx / 48, j = idx % 48;
        ws[idx] = Wu[(size_t)k * H3 + (j >> 4) * HH + c0g + (j & 15)];
    }
    for (int j = tid; j < 48; j += 256)
        brs[j] = br[(j >> 4) * HH + c0g + (j & 15)];
    __syncthreads();

    const int wrp = tid >> 5, lane = tid & 31;
    const int rbase = lane & 7;
    const int c0 = (lane >> 3) * 12;
    const int kbase = wrp * 64;
    const unsigned layerBase = (unsigned)layer * TT;

    for (int t = 0; t < TT; ++t) {
        // xp prefetch (barrier-independent)
        float pz[2], pr[2], ph[2];
#pragma unroll
        for (int q = 0; q < 2; ++q) {
            int idx = tid + q * 256;
            const float* xb = g_xp + ((size_t)(b0g + (idx >> 4)) * TT + t) * H3
                              + (c0g + (idx & 15));
            pz[q] = __ldcs(xb); pr[q] = __ldcs(xb + HH); ph[q] = __ldcs(xb + 2 * HH);
        }

        // spread-counter barrier, REDUX sum poll
        unsigned target = 32u * (layerBase + (unsigned)t);
        if (tid < 8) {
            const unsigned* cp = &g_bar2[g][tid];
            unsigned v;
            do {
                asm volatile("ld.acquire.gpu.global.u32 %0, [%1];" : "=r"(v) : "l"(cp));
            } while (__reduce_add_sync(0xffu, v) < target);
        }
        __syncthreads();

        // stage h[32][512]: coalesced LDG.128 -> STS.128 (round-9 proven form)
        const float* hsrc = g_h[t & 1];
#pragma unroll
        for (int u = 0; u < 16; ++u) {
            int it = tid + u * 256;
            int b = it >> 7, kq = it & 127;
            float4 v = __ldcg((const float4*)&hsrc[(size_t)(b0g + b) * HH + (kq << 2)]);
            *(float4*)&hs[b * HSTRIDE + (kq << 2)] = v;
        }
        __syncthreads();

        // split-K GEMM: this warp's 64-k slice of rec[32][48]
        ull acc[4][6];
#pragma unroll
        for (int i = 0; i < 4; ++i)
#pragma unroll
            for (int q = 0; q < 6; ++q) acc[i][q] = 0ull;
#pragma unroll 4
        for (int kk = 0; kk < 64; ++kk) {
            int k = kbase + kk;
            const float* hk = hs + k;
            ull A0 = dup2(hk[(rbase +  0) * HSTRIDE]);
            ull A1 = dup2(hk[(rbase +  8) * HSTRIDE]);
            ull A2 = dup2(hk[(rbase + 16) * HSTRIDE]);
            ull A3 = dup2(hk[(rbase + 24) * HSTRIDE]);
            const ulonglong2* wv = (const ulonglong2*)(ws + k * 48 + c0);
            ulonglong2 p0 = wv[0], p1 = wv[1], p2 = wv[2];
            ull w0 = p0.x, w1 = p0.y, w2 = p1.x, w3 = p1.y, w4 = p2.x, w5 = p2.y;
            ffma2(acc[0][0], A0, w0); ffma2(acc[0][1], A0, w1); ffma2(acc[0][2], A0, w2);
            ffma2(acc[0][3], A0, w3); ffma2(acc[0][4], A0, w4); ffma2(acc[0][5], A0, w5);
            ffma2(acc[1][0], A1, w0); ffma2(acc[1][1], A1, w1); ffma2(acc[1][2], A1, w2);
            ffma2(acc[1][3], A1, w3); ffma2(acc[1][4], A1, w4); ffma2(acc[1][5], A1, w5);
            ffma2(acc[2][0], A2, w0); ffma2(acc[2][1], A2, w1); ffma2(acc[2][2], A2, w2);
            ffma2(acc[2][3], A2, w3); ffma2(acc[2][4], A2, w4); ffma2(acc[2][5], A2, w5);
            ffma2(acc[3][0], A3, w0); ffma2(acc[3][1], A3, w1); ffma2(acc[3][2], A3, w2);
            ffma2(acc[3][3], A3, w3); ffma2(acc[3][4], A3, w4); ffma2(acc[3][5], A3, w5);
        }
        float* rpw = rp + wrp * (32 * 49);
#pragma unroll
        for (int i = 0; i < 4; ++i) {
            int row = rbase + 8 * i;
#pragma unroll
            for (int q = 0; q < 6; ++q) {
                float2 u = unpk(acc[i][q]);
                rpw[row * 49 + c0 + 2 * q]     = u.x;
                rpw[row * 49 + c0 + 2 * q + 1] = u.y;
            }
        }
        __syncthreads();

        // reduce + fast gates; write h, release, then y
        float* hdst = g_h[(t + 1) & 1];
        float* yout = isLast ? dout : (float*)g_y;
        float hn[2]; int gbv[2], gcv[2];
#pragma unroll
        for (int q = 0; q < 2; ++q) {
            int idx = tid + q * 256;
            int b = idx >> 4, c = idx & 15;
            gbv[q] = b0g + b; gcv[q] = c0g + c;
            int base = b * 49;
            float rz = brs[c], rr = brs[16 + c], rh = brs[32 + c];
#pragma unroll
            for (int w = 0; w < 8; ++w) {
                int o = w * 1568 + base;
                rz += rp[o + c];
                rr += rp[o + 16 + c];
                rh += rp[o + 32 + c];
            }
            float ez = __expf(-(pz[q] + rz));
            float z = __fdividef(1.0f, 1.0f + ez);
            float er = __expf(-(pr[q] + rr));
            float r = __fdividef(1.0f, 1.0f + er);
            float xa = ph[q] + r * rh;
            xa = fminf(fmaxf(xa, -15.0f), 15.0f);
            float e2 = __expf(2.0f * xa);
            float hh = __fdividef(e2 - 1.0f, e2 + 1.0f);
            float hold = hs[b * HSTRIDE + gcv[q]];
            hn[q] = z * hold + (1.0f - z) * hh;
            hdst[(size_t)gbv[q] * HH + gcv[q]] = hn[q];
        }

        __syncthreads();
        if (tid == 0)
            asm volatile("red.release.gpu.global.add.u32 [%0], %1;"
                         :: "l"(myCnt), "r"(1u) : "memory");

        // y / dout writes drain behind the release
#pragma unroll
        for (int q = 0; q < 2; ++q)
            yout[((size_t)gbv[q] * TT + t) * HH + gcv[q]] = hn[q];
    }
}

__global__ void copy_h_k(float* dout, int out_size) {
    int i = blockIdx.x * blockDim.x + threadIdx.x;
    size_t off = (size_t)BB * TT * HH;
    if (i < BB * HH && (off + i) < (size_t)out_size)
        dout[off + i] = g_h[0][i];
}

extern "C" void kernel_launch(void* const* d_in, const int* in_sizes, int n_in,
                              void* d_out, int out_size) {
    const float* x        = (const float*)d_in[0];
    const float* kernels  = (const float*)d_in[1];
    const float* rkernels = (const float*)d_in[2];
    const float* biases   = (const float*)d_in[3];
    float* out = (float*)d_out;

    cudaFuncSetAttribute(gru_layer_k, cudaFuncAttributeMaxDynamicSharedMemorySize,
                         SMEM_FLOATS * (int)sizeof(float));
    init_k<<<(BB * HH + 255) / 256, 256>>>();
    dummy_k<<<1, 32>>>();   // keep launch order: gru_layer_k stays at ncu index 5

    dim3 pgrid(H3 / 64, (BB * TT) / 128);
    for (int l = 0; l < 3; ++l) {
        proj_k<<<pgrid, 256>>>(x, kernels + (size_t)l * HH * H3,
                               biases + (size_t)l * 2 * H3, l > 0);
        gru_layer_k<<<128, 256, SMEM_FLOATS * (int)sizeof(float)>>>(
            rkernels + (size_t)l * HH * H3,
            biases + (size_t)l * 2 * H3 + H3,
            out, l, (l == 2) ? 1 : 0);
    }
    copy_h_k<<<(BB * HH + 255) / 256, 256>>>(out, out_size);
}

// round 12
// speedup vs baseline: 1.2079x; 1.0122x over previous
#include <cuda_runtime.h>
#include <math.h>

#define BB 128
#define TT 256
#define HH 512
#define H3 1536
typedef unsigned long long ull;

__device__ __forceinline__ ull dup2(float x) {
    ull r; asm("mov.b64 %0, {%1, %1};" : "=l"(r) : "f"(x)); return r;
}
__device__ __forceinline__ void ffma2(ull& d, ull a, ull b) {
    asm("fma.rn.f32x2 %0, %1, %2, %0;" : "+l"(d) : "l"(a), "l"(b));
}
__device__ __forceinline__ float2 unpk(ull v) {
    float2 f; asm("mov.b64 {%0, %1}, %2;" : "=f"(f.x), "=f"(f.y) : "l"(v)); return f;
}

__device__ float g_xp[(size_t)BB * TT * H3];
__device__ float g_y [(size_t)BB * TT * HH];
__device__ float g_h [2][BB * HH];
__device__ unsigned g_bar2[4][8];
__device__ unsigned g_dummy;

__global__ void init_k() {
    int i = blockIdx.x * blockDim.x + threadIdx.x;
    if (i < BB * HH) g_h[0][i] = 0.0f;
    if (i < 32) ((unsigned*)g_bar2)[i] = 0u;
}

__global__ void dummy_k() { if (threadIdx.x == 0) g_dummy = 0u; }

// ---- proj: double-buffered FFMA2 GEMM, tile 128x64, BK=16 -------------------
__global__ void __launch_bounds__(256, 3) proj_k(const float* __restrict__ xin,
                                                 const float* __restrict__ Wk,
                                                 const float* __restrict__ bias,
                                                 int useY)
{
    const float* Ain = useY ? (const float*)g_y : xin;
    __shared__ float As[2][16 * 128];
    __shared__ float Bs[2][16 * 64];
    const int tid = threadIdx.x;
    const int m0 = blockIdx.y * 128, n0 = blockIdx.x * 64;
    const int tx = tid & 15, ty = tid >> 4;
    const int my = ty * 8;
    const int mA = tid >> 1, kA = (tid & 1) * 8;
    const int kB = tid >> 4, nB = (tid & 15) * 4;
    const float* aptr = Ain + (size_t)(m0 + mA) * HH + kA;
    const float* bptr = Wk + (size_t)kB * H3 + n0 + nB;

    ull acc[4][4];
#pragma unroll
    for (int p = 0; p < 4; ++p)
#pragma unroll
        for (int j = 0; j < 4; ++j) acc[p][j] = 0ull;

    float4 av0 = *(const float4*)(aptr);
    float4 av1 = *(const float4*)(aptr + 4);
    float4 bv  = *(const float4*)(bptr);
    {
        float* a = As[0]; float* b = Bs[0];
        a[(kA + 0) * 128 + mA] = av0.x; a[(kA + 1) * 128 + mA] = av0.y;
        a[(kA + 2) * 128 + mA] = av0.z; a[(kA + 3) * 128 + mA] = av0.w;
        a[(kA + 4) * 128 + mA] = av1.x; a[(kA + 5) * 128 + mA] = av1.y;
        a[(kA + 6) * 128 + mA] = av1.z; a[(kA + 7) * 128 + mA] = av1.w;
        *(float4*)&b[kB * 64 + nB] = bv;
    }
    __syncthreads();

#pragma unroll 2
    for (int kt = 0; kt < 32; ++kt) {
        const int s = kt & 1;
        if (kt < 31) {
            av0 = *(const float4*)(aptr + (kt + 1) * 16);
            av1 = *(const float4*)(aptr + (kt + 1) * 16 + 4);
            bv  = *(const float4*)(bptr + (size_t)((kt + 1) * 16) * H3);
        }
        const float* a = As[s]; const float* b = Bs[s];
#pragma unroll
        for (int k = 0; k < 16; ++k) {
            const ulonglong2* ap = (const ulonglong2*)(a + k * 128 + my);
            ulonglong2 q0 = ap[0], q1 = ap[1];
            ull A0 = q0.x, A1 = q0.y, A2 = q1.x, A3 = q1.y;
            float4 w4 = *(const float4*)(b + k * 64 + tx * 4);
            ull W0 = dup2(w4.x), W1 = dup2(w4.y), W2 = dup2(w4.z), W3 = dup2(w4.w);
            ffma2(acc[0][0], A0, W0); ffma2(acc[0][1], A0, W1);
            ffma2(acc[0][2], A0, W2); ffma2(acc[0][3], A0, W3);
            ffma2(acc[1][0], A1, W0); ffma2(acc[1][1], A1, W1);
            ffma2(acc[1][2], A1, W2); ffma2(acc[1][3], A1, W3);
            ffma2(acc[2][0], A2, W0); ffma2(acc[2][1], A2, W1);
            ffma2(acc[2][2], A2, W2); ffma2(acc[2][3], A2, W3);
            ffma2(acc[3][0], A3, W0); ffma2(acc[3][1], A3, W1);
            ffma2(acc[3][2], A3, W2); ffma2(acc[3][3], A3, W3);
        }
        if (kt < 31) {
            float* an = As[s ^ 1]; float* bn = Bs[s ^ 1];
            an[(kA + 0) * 128 + mA] = av0.x; an[(kA + 1) * 128 + mA] = av0.y;
            an[(kA + 2) * 128 + mA] = av0.z; an[(kA + 3) * 128 + mA] = av0.w;
            an[(kA + 4) * 128 + mA] = av1.x; an[(kA + 5) * 128 + mA] = av1.y;
            an[(kA + 6) * 128 + mA] = av1.z; an[(kA + 7) * 128 + mA] = av1.w;
            *(float4*)&bn[kB * 64 + nB] = bv;
            __syncthreads();
        }
    }

    float4 b4 = *(const float4*)&bias[n0 + tx * 4];
    float bb[4] = {b4.x, b4.y, b4.z, b4.w};
#pragma unroll
    for (int p = 0; p < 4; ++p) {
        float2 u0 = unpk(acc[p][0]), u1 = unpk(acc[p][1]);
        float2 u2 = unpk(acc[p][2]), u3 = unpk(acc[p][3]);
        int rlo = m0 + my + 2 * p;
        float4 o0 = {u0.x + bb[0], u1.x + bb[1], u2.x + bb[2], u3.x + bb[3]};
        float4 o1 = {u0.y + bb[0], u1.y + bb[1], u2.y + bb[2], u3.y + bb[3]};
        *(float4*)&g_xp[(size_t)rlo * H3 + n0 + tx * 4] = o0;
        *(float4*)&g_xp[(size_t)(rlo + 1) * H3 + n0 + tx * 4] = o1;
    }
}

// ---- gru: round-9 form + vectorized A loads (float4 per 4-k block) ----------
#define HSTRIDE 516
#define SM_WS   (512 * 48)
#define SM_HS   (32 * HSTRIDE)
#define SM_RP   (8 * 32 * 49)
#define SMEM_FLOATS (SM_WS + SM_HS + SM_RP + 48)

__global__ void __launch_bounds__(256, 1) gru_layer_k(const float* __restrict__ Wu,
                                                      const float* __restrict__ br,
                                                      float* __restrict__ dout,
                                                      int layer, int isLast)
{
    extern __shared__ float sm[];
    float* ws  = sm;
    float* hs  = ws + SM_WS;
    float* rp  = hs + SM_HS;
    float* brs = rp + SM_RP;

    const int tid = threadIdx.x;
    const int g   = blockIdx.x >> 5;
    const int hg  = blockIdx.x & 31;
    const int b0g = g * 32, c0g = hg * 16;
    unsigned* myCnt = &g_bar2[g][hg & 7];

    for (int idx = tid; idx < SM_WS; idx += 256) {
        int k = idx / 48, j = idx % 48;
        ws[idx] = Wu[(size_t)k * H3 + (j >> 4) * HH + c0g + (j & 15)];
    }
    for (int j = tid; j < 48; j += 256)
        brs[j] = br[(j >> 4) * HH + c0g + (j & 15)];
    __syncthreads();

    const int wrp = tid >> 5, lane = tid & 31;
    const int rbase = lane & 7;
    const int c0 = (lane >> 3) * 12;
    const int kbase = wrp * 64;
    const unsigned layerBase = (unsigned)layer * TT;

    for (int t = 0; t < TT; ++t) {
        // xp prefetch (barrier-independent)
        float pz[2], pr[2], ph[2];
#pragma unroll
        for (int q = 0; q < 2; ++q) {
            int idx = tid + q * 256;
            const float* xb = g_xp + ((size_t)(b0g + (idx >> 4)) * TT + t) * H3
                              + (c0g + (idx & 15));
            pz[q] = __ldcs(xb); pr[q] = __ldcs(xb + HH); ph[q] = __ldcs(xb + 2 * HH);
        }

        // spread-counter barrier, REDUX sum poll
        unsigned target = 32u * (layerBase + (unsigned)t);
        if (tid < 8) {
            const unsigned* cp = &g_bar2[g][tid];
            unsigned v;
            do {
                asm volatile("ld.acquire.gpu.global.u32 %0, [%1];" : "=r"(v) : "l"(cp));
            } while (__reduce_add_sync(0xffu, v) < target);
        }
        __syncthreads();

        // stage h[32][512]: coalesced LDG.128 -> STS.128
        const float* hsrc = g_h[t & 1];
#pragma unroll
        for (int u = 0; u < 16; ++u) {
            int it = tid + u * 256;
            int b = it >> 7, kq = it & 127;
            float4 v = __ldcg((const float4*)&hsrc[(size_t)(b0g + b) * HH + (kq << 2)]);
            *(float4*)&hs[b * HSTRIDE + (kq << 2)] = v;
        }
        __syncthreads();

        // split-K GEMM: warp's 64-k slice; A loaded as float4 per 4-k block
        ull acc[4][6];
#pragma unroll
        for (int i = 0; i < 4; ++i)
#pragma unroll
            for (int q = 0; q < 6; ++q) acc[i][q] = 0ull;
#pragma unroll 2
        for (int kk4 = 0; kk4 < 16; ++kk4) {
            int k4 = kbase + kk4 * 4;
            float4 a0 = *(const float4*)&hs[(rbase +  0) * HSTRIDE + k4];
            float4 a1 = *(const float4*)&hs[(rbase +  8) * HSTRIDE + k4];
            float4 a2 = *(const float4*)&hs[(rbase + 16) * HSTRIDE + k4];
            float4 a3 = *(const float4*)&hs[(rbase + 24) * HSTRIDE + k4];
            const float* f0 = (const float*)&a0;
            const float* f1 = (const float*)&a1;
            const float* f2 = (const float*)&a2;
            const float* f3 = (const float*)&a3;
#pragma unroll
            for (int j = 0; j < 4; ++j) {
                ull A0 = dup2(f0[j]), A1 = dup2(f1[j]);
                ull A2 = dup2(f2[j]), A3 = dup2(f3[j]);
                const ulonglong2* wv = (const ulonglong2*)(ws + (k4 + j) * 48 + c0);
                ulonglong2 p0 = wv[0], p1 = wv[1], p2 = wv[2];
                ull w0 = p0.x, w1 = p0.y, w2 = p1.x, w3 = p1.y, w4 = p2.x, w5 = p2.y;
                ffma2(acc[0][0], A0, w0); ffma2(acc[0][1], A0, w1); ffma2(acc[0][2], A0, w2);
                ffma2(acc[0][3], A0, w3); ffma2(acc[0][4], A0, w4); ffma2(acc[0][5], A0, w5);
                ffma2(acc[1][0], A1, w0); ffma2(acc[1][1], A1, w1); ffma2(acc[1][2], A1, w2);
                ffma2(acc[1][3], A1, w3); ffma2(acc[1][4], A1, w4); ffma2(acc[1][5], A1, w5);
                ffma2(acc[2][0], A2, w0); ffma2(acc[2][1], A2, w1); ffma2(acc[2][2], A2, w2);
                ffma2(acc[2][3], A2, w3); ffma2(acc[2][4], A2, w4); ffma2(acc[2][5], A2, w5);
                ffma2(acc[3][0], A3, w0); ffma2(acc[3][1], A3, w1); ffma2(acc[3][2], A3, w2);
                ffma2(acc[3][3], A3, w3); ffma2(acc[3][4], A3, w4); ffma2(acc[3][5], A3, w5);
            }
        }
        float* rpw = rp + wrp * (32 * 49);
#pragma unroll
        for (int i = 0; i < 4; ++i) {
            int row = rbase + 8 * i;
#pragma unroll
            for (int q = 0; q < 6; ++q) {
                float2 u = unpk(acc[i][q]);
                rpw[row * 49 + c0 + 2 * q]     = u.x;
                rpw[row * 49 + c0 + 2 * q + 1] = u.y;
            }
        }
        __syncthreads();

        // reduce 8 partials + gates (library expf/tanhf: MUFU under fast-math)
        float* hdst = g_h[(t + 1) & 1];
        float* yout = isLast ? dout : (float*)g_y;
#pragma unroll
        for (int q = 0; q < 2; ++q) {
            int idx = tid + q * 256;
            int b = idx >> 4, c = idx & 15;
            int gb = b0g + b, gc = c0g + c;
            int base = b * 49;
            float rz = brs[c], rr = brs[16 + c], rh = brs[32 + c];
#pragma unroll
            for (int w = 0; w < 8; ++w) {
                int o = w * 1568 + base;
                rz += rp[o + c];
                rr += rp[o + 16 + c];
                rh += rp[o + 32 + c];
            }
            float z = 1.0f / (1.0f + expf(-(pz[q] + rz)));
            float r = 1.0f / (1.0f + expf(-(pr[q] + rr)));
            float hh = tanhf(ph[q] + r * rh);
            float hold = hs[b * HSTRIDE + gc];
            float hn = z * hold + (1.0f - z) * hh;
            hdst[(size_t)gb * HH + gc] = hn;
            yout[((size_t)gb * TT + t) * HH + gc] = hn;
        }

        __syncthreads();
        if (tid == 0)
            asm volatile("red.release.gpu.global.add.u32 [%0], %1;"
                         :: "l"(myCnt), "r"(1u) : "memory");
    }
}

__global__ void copy_h_k(float* dout, int out_size) {
    int i = blockIdx.x * blockDim.x + threadIdx.x;
    size_t off = (size_t)BB * TT * HH;
    if (i < BB * HH && (off + i) < (size_t)out_size)
        dout[off + i] = g_h[0][i];
}

extern "C" void kernel_launch(void* const* d_in, const int* in_sizes, int n_in,
                              void* d_out, int out_size) {
    const float* x        = (const float*)d_in[0];
    const float* kernels  = (const float*)d_in[1];
    const float* rkernels = (const float*)d_in[2];
    const float* biases   = (const float*)d_in[3];
    float* out = (float*)d_out;

    cudaFuncSetAttribute(gru_layer_k, cudaFuncAttributeMaxDynamicSharedMemorySize,
                         SMEM_FLOATS * (int)sizeof(float));
    init_k<<<(BB * HH + 255) / 256, 256>>>();
    dummy_k<<<1, 32>>>();   // keep launch order: gru_layer_k stays at ncu index 5

    dim3 pgrid(H3 / 64, (BB * TT) / 128);
    for (int l = 0; l < 3; ++l) {
        proj_k<<<pgrid, 256>>>(x, kernels + (size_t)l * HH * H3,
                               biases + (size_t)l * 2 * H3, l > 0);
        gru_layer_k<<<128, 256, SMEM_FLOATS * (int)sizeof(float)>>>(
            rkernels + (size_t)l * HH * H3,
            biases + (size_t)l * 2 * H3 + H3,
            out, l, (l == 2) ? 1 : 0);
    }
    copy_h_k<<<(BB * HH + 255) / 256, 256>>>(out, out_size);
}

// round 13
// speedup vs baseline: 1.2688x; 1.0504x over previous
#include <cuda_runtime.h>
#include <math.h>

#define BB 128
#define TT 256
#define HH 512
#define H3 1536
typedef unsigned long long ull;

__device__ __forceinline__ ull dup2(float x) {
    ull r; asm("mov.b64 %0, {%1, %1};" : "=l"(r) : "f"(x)); return r;
}
__device__ __forceinline__ void ffma2(ull& d, ull a, ull b) {
    asm("fma.rn.f32x2 %0, %1, %2, %0;" : "+l"(d) : "l"(a), "l"(b));
}
__device__ __forceinline__ float2 unpk(ull v) {
    float2 f; asm("mov.b64 {%0, %1}, %2;" : "=f"(f.x), "=f"(f.y) : "l"(v)); return f;
}

__device__ float g_xp[(size_t)BB * TT * H3];
__device__ float g_y [(size_t)BB * TT * HH];
__device__ float g_h [2][BB * HH];
__device__ unsigned g_bar2[4][8];
__device__ unsigned g_dummy;

__global__ void init_k() {
    int i = blockIdx.x * blockDim.x + threadIdx.x;
    if (i < BB * HH) g_h[0][i] = 0.0f;
    if (i < 32) ((unsigned*)g_bar2)[i] = 0u;
}

__global__ void dummy_k() { if (threadIdx.x == 0) g_dummy = 0u; }

// ---- proj: double-buffered FFMA2 GEMM, tile 128x64, BK=16 (confirmed win) ---
__global__ void __launch_bounds__(256, 3) proj_k(const float* __restrict__ xin,
                                                 const float* __restrict__ Wk,
                                                 const float* __restrict__ bias,
                                                 int useY)
{
    const float* Ain = useY ? (const float*)g_y : xin;
    __shared__ float As[2][16 * 128];
    __shared__ float Bs[2][16 * 64];
    const int tid = threadIdx.x;
    const int m0 = blockIdx.y * 128, n0 = blockIdx.x * 64;
    const int tx = tid & 15, ty = tid >> 4;
    const int my = ty * 8;
    const int mA = tid >> 1, kA = (tid & 1) * 8;
    const int kB = tid >> 4, nB = (tid & 15) * 4;
    const float* aptr = Ain + (size_t)(m0 + mA) * HH + kA;
    const float* bptr = Wk + (size_t)kB * H3 + n0 + nB;

    ull acc[4][4];
#pragma unroll
    for (int p = 0; p < 4; ++p)
#pragma unroll
        for (int j = 0; j < 4; ++j) acc[p][j] = 0ull;

    float4 av0 = *(const float4*)(aptr);
    float4 av1 = *(const float4*)(aptr + 4);
    float4 bv  = *(const float4*)(bptr);
    {
        float* a = As[0]; float* b = Bs[0];
        a[(kA + 0) * 128 + mA] = av0.x; a[(kA + 1) * 128 + mA] = av0.y;
        a[(kA + 2) * 128 + mA] = av0.z; a[(kA + 3) * 128 + mA] = av0.w;
        a[(kA + 4) * 128 + mA] = av1.x; a[(kA + 5) * 128 + mA] = av1.y;
        a[(kA + 6) * 128 + mA] = av1.z; a[(kA + 7) * 128 + mA] = av1.w;
        *(float4*)&b[kB * 64 + nB] = bv;
    }
    __syncthreads();

#pragma unroll 2
    for (int kt = 0; kt < 32; ++kt) {
        const int s = kt & 1;
        if (kt < 31) {
            av0 = *(const float4*)(aptr + (kt + 1) * 16);
            av1 = *(const float4*)(aptr + (kt + 1) * 16 + 4);
            bv  = *(const float4*)(bptr + (size_t)((kt + 1) * 16) * H3);
        }
        const float* a = As[s]; const float* b = Bs[s];
#pragma unroll
        for (int k = 0; k < 16; ++k) {
            const ulonglong2* ap = (const ulonglong2*)(a + k * 128 + my);
            ulonglong2 q0 = ap[0], q1 = ap[1];
            ull A0 = q0.x, A1 = q0.y, A2 = q1.x, A3 = q1.y;
            float4 w4 = *(const float4*)(b + k * 64 + tx * 4);
            ull W0 = dup2(w4.x), W1 = dup2(w4.y), W2 = dup2(w4.z), W3 = dup2(w4.w);
            ffma2(acc[0][0], A0, W0); ffma2(acc[0][1], A0, W1);
            ffma2(acc[0][2], A0, W2); ffma2(acc[0][3], A0, W3);
            ffma2(acc[1][0], A1, W0); ffma2(acc[1][1], A1, W1);
            ffma2(acc[1][2], A1, W2); ffma2(acc[1][3], A1, W3);
            ffma2(acc[2][0], A2, W0); ffma2(acc[2][1], A2, W1);
            ffma2(acc[2][2], A2, W2); ffma2(acc[2][3], A2, W3);
            ffma2(acc[3][0], A3, W0); ffma2(acc[3][1], A3, W1);
            ffma2(acc[3][2], A3, W2); ffma2(acc[3][3], A3, W3);
        }
        if (kt < 31) {
            float* an = As[s ^ 1]; float* bn = Bs[s ^ 1];
            an[(kA + 0) * 128 + mA] = av0.x; an[(kA + 1) * 128 + mA] = av0.y;
            an[(kA + 2) * 128 + mA] = av0.z; an[(kA + 3) * 128 + mA] = av0.w;
            an[(kA + 4) * 128 + mA] = av1.x; an[(kA + 5) * 128 + mA] = av1.y;
            an[(kA + 6) * 128 + mA] = av1.z; an[(kA + 7) * 128 + mA] = av1.w;
            *(float4*)&bn[kB * 64 + nB] = bv;
            __syncthreads();
        }
    }

    float4 b4 = *(const float4*)&bias[n0 + tx * 4];
    float bb[4] = {b4.x, b4.y, b4.z, b4.w};
#pragma unroll
    for (int p = 0; p < 4; ++p) {
        float2 u0 = unpk(acc[p][0]), u1 = unpk(acc[p][1]);
        float2 u2 = unpk(acc[p][2]), u3 = unpk(acc[p][3]);
        int rlo = m0 + my + 2 * p;
        float4 o0 = {u0.x + bb[0], u1.x + bb[1], u2.x + bb[2], u3.x + bb[3]};
        float4 o1 = {u0.y + bb[0], u1.y + bb[1], u2.y + bb[2], u3.y + bb[3]};
        *(float4*)&g_xp[(size_t)rlo * H3 + n0 + tx * 4] = o0;
        *(float4*)&g_xp[(size_t)(rlo + 1) * H3 + n0 + tx * 4] = o1;
    }
}

// ---- gru: EXACT round-8 form (measured 1.786 ms/layer) ----------------------
#define HSTRIDE 516
#define SM_WS   (512 * 48)
#define SM_HS   (32 * HSTRIDE)
#define SM_RP   (8 * 32 * 49)
#define SMEM_FLOATS (SM_WS + SM_HS + SM_RP + 48)

__global__ void __launch_bounds__(256, 1) gru_layer_k(const float* __restrict__ Wu,
                                                      const float* __restrict__ br,
                                                      float* __restrict__ dout,
                                                      int layer, int isLast)
{
    extern __shared__ float sm[];
    float* ws  = sm;
    float* hs  = ws + SM_WS;
    float* rp  = hs + SM_HS;
    float* brs = rp + SM_RP;

    const int tid = threadIdx.x;
    const int g   = blockIdx.x >> 5;
    const int hg  = blockIdx.x & 31;
    const int b0g = g * 32, c0g = hg * 16;
    unsigned* myCnt = &g_bar2[g][hg & 7];

    for (int idx = tid; idx < SM_WS; idx += 256) {
        int k = idx / 48, j = idx % 48;
        ws[idx] = Wu[(size_t)k * H3 + (j >> 4) * HH + c0g + (j & 15)];
    }
    for (int j = tid; j < 48; j += 256)
        brs[j] = br[(j >> 4) * HH + c0g + (j & 15)];
    __syncthreads();

    const int wrp = tid >> 5, lane = tid & 31;
    const int rbase = lane & 7;
    const int c0 = (lane >> 3) * 12;
    const int kbase = wrp * 64;
    const unsigned layerBase = (unsigned)layer * TT;

    for (int t = 0; t < TT; ++t) {
        // xp prefetch (barrier-independent)
        float pz[2], pr[2], ph[2];
#pragma unroll
        for (int q = 0; q < 2; ++q) {
            int idx = tid + q * 256;
            const float* xb = g_xp + ((size_t)(b0g + (idx >> 4)) * TT + t) * H3
                              + (c0g + (idx & 15));
            pz[q] = __ldcs(xb); pr[q] = __ldcs(xb + HH); ph[q] = __ldcs(xb + 2 * HH);
        }

        // spread-counter barrier: 8 lanes read 8 counters, butterfly-sum
        unsigned target = 32u * (layerBase + (unsigned)t);
        if (tid < 8) {
            const unsigned* cp = &g_bar2[g][tid];
            for (;;) {
                unsigned v;
                asm volatile("ld.acquire.gpu.global.u32 %0, [%1];" : "=r"(v) : "l"(cp));
                v += __shfl_xor_sync(0xffu, v, 1);
                v += __shfl_xor_sync(0xffu, v, 2);
                v += __shfl_xor_sync(0xffu, v, 4);
                if (v >= target) break;
            }
        }
        __syncthreads();

        // stage h[32][512]: coalesced LDG.128 -> STS.128, conflict-free
        const float* hsrc = g_h[t & 1];
#pragma unroll
        for (int u = 0; u < 16; ++u) {
            int it = tid + u * 256;
            int b = it >> 7, kq = it & 127;
            float4 v = __ldcg((const float4*)&hsrc[(size_t)(b0g + b) * HH + (kq << 2)]);
            *(float4*)&hs[b * HSTRIDE + (kq << 2)] = v;
        }
        __syncthreads();

        // split-K GEMM: this warp's 64-k slice of rec[32][48]
        ull acc[4][6];
#pragma unroll
        for (int i = 0; i < 4; ++i)
#pragma unroll
            for (int q = 0; q < 6; ++q) acc[i][q] = 0ull;
#pragma unroll 4
        for (int kk = 0; kk < 64; ++kk) {
            int k = kbase + kk;
            const float* hk = hs + k;
            ull A0 = dup2(hk[(rbase +  0) * HSTRIDE]);
            ull A1 = dup2(hk[(rbase +  8) * HSTRIDE]);
            ull A2 = dup2(hk[(rbase + 16) * HSTRIDE]);
            ull A3 = dup2(hk[(rbase + 24) * HSTRIDE]);
            const ulonglong2* wv = (const ulonglong2*)(ws + k * 48 + c0);
            ulonglong2 p0 = wv[0], p1 = wv[1], p2 = wv[2];
            ull w0 = p0.x, w1 = p0.y, w2 = p1.x, w3 = p1.y, w4 = p2.x, w5 = p2.y;
            ffma2(acc[0][0], A0, w0); ffma2(acc[0][1], A0, w1); ffma2(acc[0][2], A0, w2);
            ffma2(acc[0][3], A0, w3); ffma2(acc[0][4], A0, w4); ffma2(acc[0][5], A0, w5);
            ffma2(acc[1][0], A1, w0); ffma2(acc[1][1], A1, w1); ffma2(acc[1][2], A1, w2);
            ffma2(acc[1][3], A1, w3); ffma2(acc[1][4], A1, w4); ffma2(acc[1][5], A1, w5);
            ffma2(acc[2][0], A2, w0); ffma2(acc[2][1], A2, w1); ffma2(acc[2][2], A2, w2);
            ffma2(acc[2][3], A2, w3); ffma2(acc[2][4], A2, w4); ffma2(acc[2][5], A2, w5);
            ffma2(acc[3][0], A3, w0); ffma2(acc[3][1], A3, w1); ffma2(acc[3][2], A3, w2);
            ffma2(acc[3][3], A3, w3); ffma2(acc[3][4], A3, w4); ffma2(acc[3][5], A3, w5);
        }
        float* rpw = rp + wrp * (32 * 49);
#pragma unroll
        for (int i = 0; i < 4; ++i) {
            int row = rbase + 8 * i;
#pragma unroll
            for (int q = 0; q < 6; ++q) {
                float2 u = unpk(acc[i][q]);
                rpw[row * 49 + c0 + 2 * q]     = u.x;
                rpw[row * 49 + c0 + 2 * q + 1] = u.y;
            }
        }
        __syncthreads();

        // reduce 8 partials + gates + state update
        float* hdst = g_h[(t + 1) & 1];
        float* yout = isLast ? dout : (float*)g_y;
#pragma unroll
        for (int q = 0; q < 2; ++q) {
            int idx = tid + q * 256;
            int b = idx >> 4, c = idx & 15;
            int gb = b0g + b, gc = c0g + c;
            int base = b * 49;
            float rz = brs[c], rr = brs[16 + c], rh = brs[32 + c];
#pragma unroll
            for (int w = 0; w < 8; ++w) {
                int o = w * 1568 + base;
                rz += rp[o + c];
                rr += rp[o + 16 + c];
                rh += rp[o + 32 + c];
            }
            float z = 1.0f / (1.0f + expf(-(pz[q] + rz)));
            float r = 1.0f / (1.0f + expf(-(pr[q] + rr)));
            float hh = tanhf(ph[q] + r * rh);
            float hold = hs[b * HSTRIDE + gc];
            float hn = z * hold + (1.0f - z) * hh;
            hdst[(size_t)gb * HH + gc] = hn;
            yout[((size_t)gb * TT + t) * HH + gc] = hn;
        }

        // arrive: release-add to this CTA's spread counter
        __syncthreads();
        if (tid == 0)
            asm volatile("red.release.gpu.global.add.u32 [%0], %1;"
                         :: "l"(myCnt), "r"(1u) : "memory");
    }
}

__global__ void copy_h_k(float* dout, int out_size) {
    int i = blockIdx.x * blockDim.x + threadIdx.x;
    size_t off = (size_t)BB * TT * HH;
    if (i < BB * HH && (off + i) < (size_t)out_size)
        dout[off + i] = g_h[0][i];
}

extern "C" void kernel_launch(void* const* d_in, const int* in_sizes, int n_in,
                              void* d_out, int out_size) {
    const float* x        = (const float*)d_in[0];
    const float* kernels  = (const float*)d_in[1];
    const float* rkernels = (const float*)d_in[2];
    const float* biases   = (const float*)d_in[3];
    float* out = (float*)d_out;

    cudaFuncSetAttribute(gru_layer_k, cudaFuncAttributeMaxDynamicSharedMemorySize,
                         SMEM_FLOATS * (int)sizeof(float));
    init_k<<<(BB * HH + 255) / 256, 256>>>();
    dummy_k<<<1, 32>>>();   // keep launch order: gru_layer_k stays at ncu index 5

    dim3 pgrid(H3 / 64, (BB * TT) / 128);
    for (int l = 0; l < 3; ++l) {
        proj_k<<<pgrid, 256>>>(x, kernels + (size_t)l * HH * H3,
                               biases + (size_t)l * 2 * H3, l > 0);
        gru_layer_k<<<128, 256, SMEM_FLOATS * (int)sizeof(float)>>>(
            rkernels + (size_t)l * HH * H3,
            biases + (size_t)l * 2 * H3 + H3,
            out, l, (l == 2) ? 1 : 0);
    }
    copy_h_k<<<(BB * HH + 255) / 256, 256>>>(out, out_size);
}